// round 1
// baseline (speedup 1.0000x reference)
#include <cuda_runtime.h>
#include <cstdint>

// RoIAlign (torchvision semantics, aligned=false), POOLED=7, SCALE=1, SR=2.
// features: [N=2, C=256, H=200, W=200] f32, rois: [K=512, 5] f32
// out: [K, C, 7, 7] f32
//
// Strategy:
//  - 1 block per ROI (512 blocks, 256 threads).
//  - Precompute the 196 sample points (49 bins x 4 subsamples) once per block
//    into shared memory: base offset (y0*W+x0) + 4 bilinear weights with the
//    validity mask and the 1/4 mean factor pre-folded in.
//  - Threads then sweep the ROI's contiguous 256*49-element output slice in
//    49 coalesced iterations. Warp threads share a channel plane -> gathers
//    cluster in a small region of one plane (L1/L2 sector reuse), and output
//    writes are perfectly coalesced.

#define NBATCH 2
#define CCH    256
#define HH     200
#define WW     200
#define PP     7
#define KROIS  512
#define NBINS  (PP * PP)        // 49
#define NSAMP  (NBINS * 4)      // 196
#define PLANE  (HH * WW)        // 40000

__global__ __launch_bounds__(256)
void roi_align_kernel(const float* __restrict__ feat,
                      const float* __restrict__ rois,
                      float* __restrict__ out)
{
    __shared__ int    s_off[NSAMP];     // indexed [s*49 + pp]
    __shared__ float4 s_w[NSAMP];       // indexed [s*49 + pp]
    __shared__ int    s_b;

    const int k   = blockIdx.x;
    const int tid = threadIdx.x;

    // --- per-ROI setup -------------------------------------------------
    const float r0 = rois[k * 5 + 0];
    const float x1 = rois[k * 5 + 1];
    const float y1 = rois[k * 5 + 2];
    const float x2 = rois[k * 5 + 3];
    const float y2 = rois[k * 5 + 4];

    const float roi_w = fmaxf(x2 - x1, 1.0f);
    const float roi_h = fmaxf(y2 - y1, 1.0f);
    const float bin_w = roi_w * (1.0f / PP);
    const float bin_h = roi_h * (1.0f / PP);

    if (tid == 0) s_b = (int)r0;

    if (tid < NSAMP) {
        const int s  = tid / NBINS;      // subsample 0..3  (sy*2+sx)
        const int pp = tid - s * NBINS;  // bin 0..48       (ph*7+pw)
        const int ph = pp / PP;
        const int pw = pp - ph * PP;
        const int sy = s >> 1;
        const int sx = s & 1;

        const float gy = (float)ph + ((float)sy + 0.5f) * 0.5f;
        const float gx = (float)pw + ((float)sx + 0.5f) * 0.5f;
        float y = y1 + gy * bin_h;
        float x = x1 + gx * bin_w;

        const bool valid = (y >= -1.0f) && (y <= (float)HH) &&
                           (x >= -1.0f) && (x <= (float)WW);

        y = fminf(fmaxf(y, 0.0f), (float)(HH - 1));
        x = fminf(fmaxf(x, 0.0f), (float)(WW - 1));

        int y0 = (int)floorf(y); if (y0 > HH - 2) y0 = HH - 2;
        int x0 = (int)floorf(x); if (x0 > WW - 2) x0 = WW - 2;

        const float ly = y - (float)y0;
        const float lx = x - (float)x0;
        const float hy = 1.0f - ly;
        const float hx = 1.0f - lx;
        const float vs = valid ? 0.25f : 0.0f;   // fold mean(1/4) + validity

        const int si = s * NBINS + pp;
        s_off[si] = y0 * WW + x0;
        s_w[si]   = make_float4(hy * hx * vs, hy * lx * vs,
                                ly * hx * vs, ly * lx * vs);
    }
    __syncthreads();

    const float* __restrict__ fb = feat + (size_t)s_b * (CCH * PLANE);
    float* __restrict__       ob = out  + (size_t)k   * (CCH * NBINS);

    // 256 channels * 49 bins = 12544 outputs = 49 iterations of 256 threads.
    // idx = it*256 + tid; c = idx/49, pp = idx%49  (incremental update).
    int idx0 = tid;
    int c    = idx0 / NBINS;
    int pp   = idx0 - c * NBINS;

    #pragma unroll 1
    for (int it = 0; it < 49; ++it) {
        const float* __restrict__ fc = fb + (size_t)c * PLANE;
        float acc = 0.0f;

        #pragma unroll
        for (int s = 0; s < 4; ++s) {
            const int    si = s * NBINS + pp;
            const int    o  = s_off[si];
            const float4 w  = s_w[si];
            const float* p  = fc + o;
            acc += w.x * p[0]
                 + w.y * p[1]
                 + w.z * p[WW]
                 + w.w * p[WW + 1];
        }

        ob[it * 256 + tid] = acc;

        // advance idx by 256: 256 = 5*49 + 11
        pp += 11;
        c  += 5;
        if (pp >= NBINS) { pp -= NBINS; c += 1; }
    }
}

extern "C" void kernel_launch(void* const* d_in, const int* in_sizes, int n_in,
                              void* d_out, int out_size)
{
    const float* feat = (const float*)d_in[0];
    const float* rois = (const float*)d_in[1];
    float*       out  = (float*)d_out;

    roi_align_kernel<<<KROIS, 256>>>(feat, rois, out);
}

// round 2
// speedup vs baseline: 1.2479x; 1.2479x over previous
#include <cuda_runtime.h>
#include <cstdint>

// RoIAlign (torchvision, aligned=false), POOLED=7, SCALE=1, SR=2.
// features: [N=2, C=256, H=200, W=200] f32, rois: [K=512, 5] f32
// out: [K, C, 7, 7] f32
//
// R2: grid (512 rois, 4 channel-chunks), 224 threads/block.
//  - Each block: 64 channels x 49 bins = 3136 outputs = 224 x 14 exact.
//  - Fixes grid-limited occupancy (R1: 3.46 blocks/SM -> 42% occ).
//  - Sample table (196 entries) computed once per block in one pass.

#define CCH    256
#define HH     200
#define WW     200
#define PP     7
#define KROIS  512
#define NBINS  (PP * PP)        // 49
#define NSAMP  (NBINS * 4)      // 196
#define PLANE  (HH * WW)        // 40000
#define CSPLIT 4
#define CCHUNK (CCH / CSPLIT)   // 64
#define TPB    224              // 3136 / 14
#define NITER  14

__global__ __launch_bounds__(TPB)
void roi_align_kernel(const float* __restrict__ feat,
                      const float* __restrict__ rois,
                      float* __restrict__ out)
{
    __shared__ int    s_off[NSAMP];     // [s*49 + pp]
    __shared__ float4 s_w[NSAMP];       // [s*49 + pp]
    __shared__ int    s_b;

    const int k     = blockIdx.x;
    const int cbase = blockIdx.y * CCHUNK;
    const int tid   = threadIdx.x;

    // --- per-ROI sample table -----------------------------------------
    const float r0 = rois[k * 5 + 0];
    const float x1 = rois[k * 5 + 1];
    const float y1 = rois[k * 5 + 2];
    const float x2 = rois[k * 5 + 3];
    const float y2 = rois[k * 5 + 4];

    const float roi_w = fmaxf(x2 - x1, 1.0f);
    const float roi_h = fmaxf(y2 - y1, 1.0f);
    const float bin_w = roi_w * (1.0f / PP);
    const float bin_h = roi_h * (1.0f / PP);

    if (tid == 0) s_b = (int)r0;

    if (tid < NSAMP) {
        const int s  = tid / NBINS;      // subsample 0..3 (sy*2+sx)
        const int pp = tid - s * NBINS;  // bin 0..48      (ph*7+pw)
        const int ph = pp / PP;
        const int pw = pp - ph * PP;
        const int sy = s >> 1;
        const int sx = s & 1;

        const float gy = (float)ph + ((float)sy + 0.5f) * 0.5f;
        const float gx = (float)pw + ((float)sx + 0.5f) * 0.5f;
        float y = y1 + gy * bin_h;
        float x = x1 + gx * bin_w;

        const bool valid = (y >= -1.0f) && (y <= (float)HH) &&
                           (x >= -1.0f) && (x <= (float)WW);

        y = fminf(fmaxf(y, 0.0f), (float)(HH - 1));
        x = fminf(fmaxf(x, 0.0f), (float)(WW - 1));

        int y0 = (int)floorf(y); if (y0 > HH - 2) y0 = HH - 2;
        int x0 = (int)floorf(x); if (x0 > WW - 2) x0 = WW - 2;

        const float ly = y - (float)y0;
        const float lx = x - (float)x0;
        const float hy = 1.0f - ly;
        const float hx = 1.0f - lx;
        const float vs = valid ? 0.25f : 0.0f;   // fold mean(1/4) + validity

        const int si = s * NBINS + pp;
        s_off[si] = y0 * WW + x0;
        s_w[si]   = make_float4(hy * hx * vs, hy * lx * vs,
                                ly * hx * vs, ly * lx * vs);
    }
    __syncthreads();

    const float* __restrict__ fb = feat + (size_t)s_b * (CCH * PLANE)
                                        + (size_t)cbase * PLANE;
    float* __restrict__       ob = out  + (size_t)k * (CCH * NBINS)
                                        + (size_t)cbase * NBINS;

    // 64 channels * 49 bins = 3136 outputs = 14 iterations of 224 threads.
    int c  = tid / NBINS;           // local channel 0..63
    int pp = tid - c * NBINS;

    #pragma unroll 1
    for (int it = 0; it < NITER; ++it) {
        const float* __restrict__ fc = fb + (size_t)c * PLANE;
        float acc = 0.0f;

        #pragma unroll
        for (int s = 0; s < 4; ++s) {
            const int    si = s * NBINS + pp;
            const int    o  = s_off[si];
            const float4 w  = s_w[si];
            const float* p  = fc + o;
            acc += w.x * p[0]
                 + w.y * p[1]
                 + w.z * p[WW]
                 + w.w * p[WW + 1];
        }

        ob[it * TPB + tid] = acc;

        // advance linear index by 224 = 4*49 + 28
        pp += 28;
        c  += 4;
        if (pp >= NBINS) { pp -= NBINS; c += 1; }
    }
}

extern "C" void kernel_launch(void* const* d_in, const int* in_sizes, int n_in,
                              void* d_out, int out_size)
{
    const float* feat = (const float*)d_in[0];
    const float* rois = (const float*)d_in[1];
    float*       out  = (float*)d_out;

    dim3 grid(KROIS, CSPLIT);
    roi_align_kernel<<<grid, TPB>>>(feat, rois, out);
}

// round 3
// speedup vs baseline: 1.9409x; 1.5552x over previous
#include <cuda_runtime.h>
#include <cstdint>

// RoIAlign (torchvision, aligned=false), POOLED=7, SCALE=1, SR=2.
// features: [2,256,200,200] f32, rois: [512,5] f32, out: [512,256,7,7] f32
//
// R3: warp = one bin-row of one channel; lane = pw*4 + sample.
//  - Each gather instruction's footprint = 2 sample-ys x (roi_w span) ~= 4
//    cache lines (vs ~10 for the R2 mapping) -> ~2x fewer l1tex wavefronts.
//  - 4 sample contributions combined with shfl_xor(1), shfl_xor(2).
//  - Block: 224 thr (7 warps = 7 bin-rows), loops 32 channels (x2 unroll).
//  - Grid: (512 rois, 8 channel-chunks) = 4096 blocks.

#define CCH    256
#define HH     200
#define WW     200
#define PP     7
#define KROIS  512
#define NBINS  (PP * PP)        // 49
#define NSAMP  (NBINS * 4)      // 196
#define PLANE  (HH * WW)        // 40000
#define CSPLIT 8
#define CCHUNK (CCH / CSPLIT)   // 32
#define TPB    224              // 7 warps

__global__ __launch_bounds__(TPB)
void roi_align_kernel(const float* __restrict__ feat,
                      const float* __restrict__ rois,
                      float* __restrict__ out)
{
    __shared__ int    s_off[NSAMP];     // [pp*4 + s]
    __shared__ float4 s_w[NSAMP];       // [pp*4 + s]
    __shared__ int    s_b;

    const int k     = blockIdx.x;
    const int cbase = blockIdx.y * CCHUNK;
    const int tid   = threadIdx.x;

    // --- per-ROI sample table (layout [pp][s] for sequential warp LDS) ---
    const float r0 = rois[k * 5 + 0];
    const float x1 = rois[k * 5 + 1];
    const float y1 = rois[k * 5 + 2];
    const float x2 = rois[k * 5 + 3];
    const float y2 = rois[k * 5 + 4];

    const float roi_w = fmaxf(x2 - x1, 1.0f);
    const float roi_h = fmaxf(y2 - y1, 1.0f);
    const float bin_w = roi_w * (1.0f / PP);
    const float bin_h = roi_h * (1.0f / PP);

    if (tid == 0) s_b = (int)r0;

    if (tid < NSAMP) {
        const int pp = tid >> 2;         // bin 0..48 (ph*7+pw)
        const int s  = tid & 3;          // sample 0..3 (sy*2+sx)
        const int ph = pp / PP;
        const int pw = pp - ph * PP;
        const int sy = s >> 1;
        const int sx = s & 1;

        const float gy = (float)ph + ((float)sy + 0.5f) * 0.5f;
        const float gx = (float)pw + ((float)sx + 0.5f) * 0.5f;
        float y = y1 + gy * bin_h;
        float x = x1 + gx * bin_w;

        const bool valid = (y >= -1.0f) && (y <= (float)HH) &&
                           (x >= -1.0f) && (x <= (float)WW);

        y = fminf(fmaxf(y, 0.0f), (float)(HH - 1));
        x = fminf(fmaxf(x, 0.0f), (float)(WW - 1));

        int y0 = (int)floorf(y); if (y0 > HH - 2) y0 = HH - 2;
        int x0 = (int)floorf(x); if (x0 > WW - 2) x0 = WW - 2;

        const float ly = y - (float)y0;
        const float lx = x - (float)x0;
        const float hy = 1.0f - ly;
        const float hx = 1.0f - lx;
        const float vs = valid ? 0.25f : 0.0f;   // fold mean(1/4) + validity

        s_off[tid] = y0 * WW + x0;
        s_w[tid]   = make_float4(hy * hx * vs, hy * lx * vs,
                                 ly * hx * vs, ly * lx * vs);
    }
    __syncthreads();

    const int warp = tid >> 5;           // 0..6 = bin-row ph
    const int lane = tid & 31;
    const int pw   = lane >> 2;          // 0..7 (7 valid)
    const bool act = (lane < 28);
    const int pp   = warp * PP + (act ? pw : 6);
    const int si   = pp * 4 + (lane & 3);

    const int    o = s_off[si];
    const float4 w = s_w[si];

    const float* __restrict__ fb = feat + (size_t)s_b * (CCH * PLANE)
                                        + (size_t)cbase * PLANE;
    float* __restrict__       ob = out  + (size_t)k * (CCH * NBINS)
                                        + (size_t)cbase * NBINS;

    const bool wr = act && ((lane & 3) == 0);

    #pragma unroll 1
    for (int c = 0; c < CCHUNK; c += 2) {
        const float* p0 = fb + (size_t)c * PLANE + o;
        const float* p1 = p0 + PLANE;

        float v0 = 0.0f, v1 = 0.0f;
        if (act) {
            v0 = w.x * p0[0] + w.y * p0[1] + w.z * p0[WW] + w.w * p0[WW + 1];
            v1 = w.x * p1[0] + w.y * p1[1] + w.z * p1[WW] + w.w * p1[WW + 1];
        }
        v0 += __shfl_xor_sync(0xFFFFFFFFu, v0, 1);
        v0 += __shfl_xor_sync(0xFFFFFFFFu, v0, 2);
        v1 += __shfl_xor_sync(0xFFFFFFFFu, v1, 1);
        v1 += __shfl_xor_sync(0xFFFFFFFFu, v1, 2);

        if (wr) {
            ob[(size_t)c * NBINS + pp]       = v0;
            ob[(size_t)(c + 1) * NBINS + pp] = v1;
        }
    }
}

extern "C" void kernel_launch(void* const* d_in, const int* in_sizes, int n_in,
                              void* d_out, int out_size)
{
    const float* feat = (const float*)d_in[0];
    const float* rois = (const float*)d_in[1];
    float*       out  = (float*)d_out;

    dim3 grid(KROIS, CSPLIT);
    roi_align_kernel<<<grid, TPB>>>(feat, rois, out);
}

// round 4
// speedup vs baseline: 2.1346x; 1.0998x over previous
#include <cuda_runtime.h>
#include <cstdint>

// RoIAlign (torchvision, aligned=false), POOLED=7, SCALE=1, SR=2.
// features: [2,256,200,200] f32, rois: [512,5] f32, out: [512,256,7,7] f32
//
// R4: R3 mapping (warp = bin-row, lane = pw*4+sample, shfl-combine) with
// channel loop unrolled x4 -> 16 independent gathers in flight per lane.
// Channel pointers differ by constant PLANE offsets from one base, so SASS
// uses immediate offsets (1 addr reg) and registers stay ~30.

#define CCH    256
#define HH     200
#define WW     200
#define PP     7
#define KROIS  512
#define NBINS  (PP * PP)        // 49
#define NSAMP  (NBINS * 4)      // 196
#define PLANE  (HH * WW)        // 40000
#define CSPLIT 8
#define CCHUNK (CCH / CSPLIT)   // 32
#define TPB    224              // 7 warps

__global__ __launch_bounds__(TPB, 8)
void roi_align_kernel(const float* __restrict__ feat,
                      const float* __restrict__ rois,
                      float* __restrict__ out)
{
    __shared__ int    s_off[NSAMP];     // [pp*4 + s]
    __shared__ float4 s_w[NSAMP];       // [pp*4 + s]
    __shared__ int    s_b;

    const int k     = blockIdx.x;
    const int cbase = blockIdx.y * CCHUNK;
    const int tid   = threadIdx.x;

    // --- per-ROI sample table (layout [pp][s]) -------------------------
    const float r0 = rois[k * 5 + 0];
    const float x1 = rois[k * 5 + 1];
    const float y1 = rois[k * 5 + 2];
    const float x2 = rois[k * 5 + 3];
    const float y2 = rois[k * 5 + 4];

    const float roi_w = fmaxf(x2 - x1, 1.0f);
    const float roi_h = fmaxf(y2 - y1, 1.0f);
    const float bin_w = roi_w * (1.0f / PP);
    const float bin_h = roi_h * (1.0f / PP);

    if (tid == 0) s_b = (int)r0;

    if (tid < NSAMP) {
        const int pp = tid >> 2;         // bin 0..48 (ph*7+pw)
        const int s  = tid & 3;          // sample 0..3 (sy*2+sx)
        const int ph = pp / PP;
        const int pw = pp - ph * PP;
        const int sy = s >> 1;
        const int sx = s & 1;

        const float gy = (float)ph + ((float)sy + 0.5f) * 0.5f;
        const float gx = (float)pw + ((float)sx + 0.5f) * 0.5f;
        float y = y1 + gy * bin_h;
        float x = x1 + gx * bin_w;

        const bool valid = (y >= -1.0f) && (y <= (float)HH) &&
                           (x >= -1.0f) && (x <= (float)WW);

        y = fminf(fmaxf(y, 0.0f), (float)(HH - 1));
        x = fminf(fmaxf(x, 0.0f), (float)(WW - 1));

        int y0 = (int)floorf(y); if (y0 > HH - 2) y0 = HH - 2;
        int x0 = (int)floorf(x); if (x0 > WW - 2) x0 = WW - 2;

        const float ly = y - (float)y0;
        const float lx = x - (float)x0;
        const float hy = 1.0f - ly;
        const float hx = 1.0f - lx;
        const float vs = valid ? 0.25f : 0.0f;   // fold mean(1/4) + validity

        s_off[tid] = y0 * WW + x0;
        s_w[tid]   = make_float4(hy * hx * vs, hy * lx * vs,
                                 ly * hx * vs, ly * lx * vs);
    }
    __syncthreads();

    const int warp = tid >> 5;           // 0..6 = bin-row ph
    const int lane = tid & 31;
    const int pw   = lane >> 2;          // 0..7 (7 valid)
    const bool act = (lane < 28);
    const int pp   = warp * PP + (act ? pw : 6);
    const int si   = pp * 4 + (lane & 3);

    const int    o = s_off[si];
    const float4 w = s_w[si];

    const float* __restrict__ fb = feat + (size_t)s_b * (CCH * PLANE)
                                        + (size_t)cbase * PLANE;
    float* __restrict__       ob = out  + (size_t)k * (CCH * NBINS)
                                        + (size_t)cbase * NBINS;

    const bool wr = act && ((lane & 3) == 0);

    #pragma unroll 1
    for (int c = 0; c < CCHUNK; c += 4) {
        const float* p = fb + (size_t)c * PLANE + o;

        float a0 = 0.f, b0 = 0.f, c0 = 0.f, d0 = 0.f;
        float a1 = 0.f, b1 = 0.f, c1 = 0.f, d1 = 0.f;
        float a2 = 0.f, b2 = 0.f, c2 = 0.f, d2 = 0.f;
        float a3 = 0.f, b3 = 0.f, c3 = 0.f, d3 = 0.f;
        if (act) {
            // 16 independent gathers; constant immediate offsets off one base.
            a0 = p[0];             b0 = p[1];
            c0 = p[WW];            d0 = p[WW + 1];
            a1 = p[PLANE];         b1 = p[PLANE + 1];
            c1 = p[PLANE + WW];    d1 = p[PLANE + WW + 1];
            a2 = p[2 * PLANE];     b2 = p[2 * PLANE + 1];
            c2 = p[2 * PLANE + WW];d2 = p[2 * PLANE + WW + 1];
            a3 = p[3 * PLANE];     b3 = p[3 * PLANE + 1];
            c3 = p[3 * PLANE + WW];d3 = p[3 * PLANE + WW + 1];
        }

        float v0 = w.x * a0 + w.y * b0 + w.z * c0 + w.w * d0;
        float v1 = w.x * a1 + w.y * b1 + w.z * c1 + w.w * d1;
        float v2 = w.x * a2 + w.y * b2 + w.z * c2 + w.w * d2;
        float v3 = w.x * a3 + w.y * b3 + w.z * c3 + w.w * d3;

        v0 += __shfl_xor_sync(0xFFFFFFFFu, v0, 1);
        v1 += __shfl_xor_sync(0xFFFFFFFFu, v1, 1);
        v2 += __shfl_xor_sync(0xFFFFFFFFu, v2, 1);
        v3 += __shfl_xor_sync(0xFFFFFFFFu, v3, 1);
        v0 += __shfl_xor_sync(0xFFFFFFFFu, v0, 2);
        v1 += __shfl_xor_sync(0xFFFFFFFFu, v1, 2);
        v2 += __shfl_xor_sync(0xFFFFFFFFu, v2, 2);
        v3 += __shfl_xor_sync(0xFFFFFFFFu, v3, 2);

        if (wr) {
            ob[(size_t)(c + 0) * NBINS + pp] = v0;
            ob[(size_t)(c + 1) * NBINS + pp] = v1;
            ob[(size_t)(c + 2) * NBINS + pp] = v2;
            ob[(size_t)(c + 3) * NBINS + pp] = v3;
        }
    }
}

extern "C" void kernel_launch(void* const* d_in, const int* in_sizes, int n_in,
                              void* d_out, int out_size)
{
    const float* feat = (const float*)d_in[0];
    const float* rois = (const float*)d_in[1];
    float*       out  = (float*)d_out;

    dim3 grid(KROIS, CSPLIT);
    roi_align_kernel<<<grid, TPB>>>(feat, rois, out);
}